// round 4
// baseline (speedup 1.0000x reference)
#include <cuda_runtime.h>
#include <cuda_bf16.h>

// Problem constants
#define NB 128          // graphs
#define NN 512          // nodes per graph
#define NNODES (NB*NN)  // 65536
#define NE 524288       // edges
#define EPG 4096        // edges per graph
#define EPT 8           // edges per thread in build (4096/512)
#define F_IN 128
#define H1 64
#define H2 128
#define NC 10
#define KSEL 410        // ceil(0.8*512)

// ---------------- scratch (static device globals; no allocation) ----------------
__device__ __align__(16) int   g_rowstart[NNODES];  // per-node exclusive offset within graph
__device__ __align__(16) int   g_deg[NNODES];
__device__ __align__(16) int   g_col[NE];           // local src ids, grouped per graph
__device__ __align__(16) float g_dis[NNODES];
__device__ __align__(16) float g_h1[NNODES * H1];
__device__ __align__(16) float g_out1[NNODES * H1];
__device__ __align__(16) float g_a2[NNODES * H1];
__device__ __align__(16) float g_out2[NNODES * H2];
__device__ __align__(16) float g_score[NNODES];
__device__ __align__(16) float g_gmax[NB * H2];

// ---------------- fused per-graph CSR build ----------------
// one block per graph, 512 threads; smem atomics + smem scan + smem-offset scatter
__global__ void k_build(const int* __restrict__ ei) {
    __shared__ int cnt[NN];
    __shared__ int scn[NN];
    __shared__ int fill[NN];
    int b = blockIdx.x, t = threadIdx.x;
    cnt[t] = 0;
    __syncthreads();

    int ebase = b * EPG;
    int sl[EPT], dl[EPT];
    #pragma unroll
    for (int j = 0; j < EPT; j++) {
        int e = ebase + j * NN + t;           // coalesced
        sl[j] = ei[e] & (NN - 1);             // local ids (graph offset removed by mask)
        dl[j] = ei[NE + e] & (NN - 1);
        atomicAdd(&cnt[dl[j]], 1);
    }
    __syncthreads();

    int c = cnt[t];
    scn[t] = c;
    __syncthreads();
    #pragma unroll
    for (int off = 1; off < NN; off <<= 1) {
        int v = (t >= off) ? scn[t - off] : 0;
        __syncthreads();
        scn[t] += v;
        __syncthreads();
    }
    int excl = scn[t] - c;
    int gv = b * NN + t;
    g_rowstart[gv] = excl;
    g_deg[gv] = c;
    g_dis[gv] = rsqrtf((float)(c + 1));       // +1 self loop
    fill[t] = excl;
    __syncthreads();

    #pragma unroll
    for (int j = 0; j < EPT; j++) {
        int pos = atomicAdd(&fill[dl[j]], 1);
        g_col[ebase + pos] = sl[j];
    }
}

// ---------------- GEMM1: g_h1[65536,64] = X[65536,128] @ W1[128,64] ----------------
__global__ void k_gemm1(const float* __restrict__ X, const float* __restrict__ W) {
    __shared__ float Ws[F_IN * H1];    // 32 KB
    __shared__ float Xs[32 * F_IN];    // 16 KB
    int tx = threadIdx.x, ty = threadIdx.y;
    int t = ty * 16 + tx;
    int row0 = blockIdx.x * 32;

    float4* Ws4 = (float4*)Ws;
    const float4* Wg = (const float4*)W;
    #pragma unroll
    for (int l = t; l < (F_IN * H1) / 4; l += 128) Ws4[l] = Wg[l];

    float4* Xs4 = (float4*)Xs;
    const float4* Xg = (const float4*)(X + (size_t)row0 * F_IN);
    #pragma unroll
    for (int l = t; l < (32 * F_IN) / 4; l += 128) Xs4[l] = Xg[l];
    __syncthreads();

    float acc[4][4];
    #pragma unroll
    for (int r = 0; r < 4; r++)
        #pragma unroll
        for (int c = 0; c < 4; c++) acc[r][c] = 0.f;

    #pragma unroll 4
    for (int k = 0; k < F_IN; k += 4) {
        float4 xq[4];
        #pragma unroll
        for (int r = 0; r < 4; r++) xq[r] = Xs4[(ty * 4 + r) * (F_IN / 4) + k / 4];
        #pragma unroll
        for (int kk = 0; kk < 4; kk++) {
            float4 w = Ws4[(k + kk) * (H1 / 4) + tx];
            #pragma unroll
            for (int r = 0; r < 4; r++) {
                float xv = (kk == 0) ? xq[r].x : (kk == 1) ? xq[r].y : (kk == 2) ? xq[r].z : xq[r].w;
                acc[r][0] += xv * w.x;
                acc[r][1] += xv * w.y;
                acc[r][2] += xv * w.z;
                acc[r][3] += xv * w.w;
            }
        }
    }
    #pragma unroll
    for (int r = 0; r < 4; r++) {
        float4 o = make_float4(acc[r][0], acc[r][1], acc[r][2], acc[r][3]);
        ((float4*)g_h1)[((size_t)(row0 + ty * 4 + r) * H1 + tx * 4) / 4] = o;
    }
}

// ---------------- smem-staged gather, one (graph, feature-half) per block ----------------
// PASS 0: g_out1 = relu( Agg(g_h1) + b1 );  PASS 1: g_a2 = Agg(g_out1)
// Agg(h)[v] = sum_{s in in(v)} dis[s]*dis[v]*h[s] + dis[v]^2 * h[v]
template <int PASS>
__global__ void k_gather_s(const float* __restrict__ bias) {
    extern __shared__ float smem[];
    float* hs   = smem;            // 512 nodes x 32 feats = 64 KB
    float* diss = smem + NN * 32;  // 512 floats
    const float* __restrict__ h   = (PASS == 0) ? g_h1   : g_out1;
    float* __restrict__       out = (PASS == 0) ? g_out1 : g_a2;

    int b = blockIdx.x, half = blockIdx.y, t = threadIdx.x;  // 512 threads
    int gbase = b * NN;

    // stage features: smem layout [node][32]; global row = 64 floats (16 float4)
    float4* hs4 = (float4*)hs;
    const float4* g4 = (const float4*)h;
    #pragma unroll
    for (int j = 0; j < 8; j++) {
        int f = j * NN + t;        // 0..4095 over (node, q) with q = f & 7
        int node = f >> 3, q = f & 7;
        hs4[f] = g4[(size_t)(gbase + node) * 16 + half * 8 + q];
    }
    diss[t] = g_dis[gbase + t];
    __syncthreads();

    int warp = t >> 5, lane = t & 31;
    #pragma unroll 1
    for (int vl = warp; vl < NN; vl += 16) {
        float dv = diss[vl];
        int beg = g_rowstart[gbase + vl];
        int deg = g_deg[gbase + vl];
        float a = dv * dv * hs[vl * 32 + lane];
        int eb = b * EPG + beg;
        for (int e = 0; e < deg; e++) {
            int s = g_col[eb + e];
            a += dv * diss[s] * hs[s * 32 + lane];
        }
        if (PASS == 0) a = fmaxf(a + bias[half * 32 + lane], 0.f);
        out[(size_t)(gbase + vl) * H1 + half * 32 + lane] = a;
    }
}

// ---------------- GEMM2 + fused score: g_out2 = relu(g_a2 @ W2 + b2), g_score = out2.pw/||pw|| ----------------
// tile 64 rows x 128 cols, block (32,8)=256 thr; warp = fixed ty owns 8 full rows
__global__ void k_gemm2(const float* __restrict__ W, const float* __restrict__ bias,
                        const float* __restrict__ pw) {
    __shared__ float Ws[H1 * H2];   // 32 KB
    __shared__ float Xs[64 * H1];   // 16 KB
    int tx = threadIdx.x, ty = threadIdx.y;
    int t = ty * 32 + tx;
    int row0 = blockIdx.x * 64;

    float4* Ws4 = (float4*)Ws;
    const float4* Wg = (const float4*)W;
    #pragma unroll
    for (int l = t; l < (H1 * H2) / 4; l += 256) Ws4[l] = Wg[l];

    float4* Xs4 = (float4*)Xs;
    const float4* Ag = (const float4*)(g_a2 + (size_t)row0 * H1);
    #pragma unroll
    for (int l = t; l < (64 * H1) / 4; l += 256) Xs4[l] = Ag[l];
    __syncthreads();

    float acc[8][4];
    #pragma unroll
    for (int r = 0; r < 8; r++)
        #pragma unroll
        for (int c = 0; c < 4; c++) acc[r][c] = 0.f;

    #pragma unroll 2
    for (int k = 0; k < H1; k += 4) {
        float4 xq[8];
        #pragma unroll
        for (int r = 0; r < 8; r++) xq[r] = Xs4[(ty * 8 + r) * (H1 / 4) + k / 4];
        #pragma unroll
        for (int kk = 0; kk < 4; kk++) {
            float4 w = Ws4[(k + kk) * (H2 / 4) + tx];
            #pragma unroll
            for (int r = 0; r < 8; r++) {
                float xv = (kk == 0) ? xq[r].x : (kk == 1) ? xq[r].y : (kk == 2) ? xq[r].z : xq[r].w;
                acc[r][0] += xv * w.x;
                acc[r][1] += xv * w.y;
                acc[r][2] += xv * w.z;
                acc[r][3] += xv * w.w;
            }
        }
    }

    float4 bq = ((const float4*)bias)[tx];
    float4 p  = ((const float4*)pw)[tx];
    float nn = p.x * p.x + p.y * p.y + p.z * p.z + p.w * p.w;
    #pragma unroll
    for (int off = 16; off > 0; off >>= 1) nn += __shfl_xor_sync(0xffffffffu, nn, off);
    float rn = rsqrtf(nn);

    #pragma unroll
    for (int r = 0; r < 8; r++) {
        float4 o;
        o.x = fmaxf(acc[r][0] + bq.x, 0.f);
        o.y = fmaxf(acc[r][1] + bq.y, 0.f);
        o.z = fmaxf(acc[r][2] + bq.z, 0.f);
        o.w = fmaxf(acc[r][3] + bq.w, 0.f);
        int row = row0 + ty * 8 + r;
        ((float4*)g_out2)[((size_t)row * H2 + tx * 4) / 4] = o;
        float sp = o.x * p.x + o.y * p.y + o.z * p.z + o.w * p.w;
        #pragma unroll
        for (int off = 16; off > 0; off >>= 1) sp += __shfl_xor_sync(0xffffffffu, sp, off);
        if (tx == 0) g_score[row] = sp * rn;
    }
}

// ---------------- top-K selection + gated global max pool, one block per graph ----------------
__global__ void k_pool() {
    __shared__ float s[NN];
    __shared__ float gate[NN];
    __shared__ int   sel[NN];
    __shared__ float red[NN];
    int b = blockIdx.x;
    int t = threadIdx.x;           // 512 threads
    float v = g_score[(size_t)b * NN + t];
    s[t] = v;
    __syncthreads();
    int rank = 0;
    for (int j = 0; j < NN; j++) {
        float u = s[j];
        rank += (u > v) || (u == v && j < t);
    }
    sel[t] = (rank < KSEL);
    gate[t] = tanhf(v);
    __syncthreads();
    int f = t & 127, ch = t >> 7;  // 4 chunks of 128 nodes each
    float m = -INFINITY;
    const float* base = g_out2 + ((size_t)b * NN) * H2;
    for (int i = ch * 128; i < ch * 128 + 128; i++) {
        if (sel[i]) m = fmaxf(m, base[(size_t)i * H2 + f] * gate[i]);
    }
    red[t] = m;
    __syncthreads();
    if (ch == 0) {
        float mm = fmaxf(fmaxf(red[f], red[f + 128]), fmaxf(red[f + 256], red[f + 384]));
        g_gmax[(size_t)b * H2 + f] = mm;
    }
}

// ---------------- FC + log_softmax, one thread per graph ----------------
__global__ void k_fc(const float* __restrict__ fcW, const float* __restrict__ fcb,
                     float* __restrict__ out) {
    int b = threadIdx.x;   // 128
    float acc[NC];
    #pragma unroll
    for (int c = 0; c < NC; c++) acc[c] = fcb[c];
    for (int k = 0; k < H2; k++) {
        float gv = g_gmax[(size_t)b * H2 + k];
        #pragma unroll
        for (int c = 0; c < NC; c++) acc[c] += gv * fcW[k * NC + c];
    }
    float m = acc[0];
    #pragma unroll
    for (int c = 1; c < NC; c++) m = fmaxf(m, acc[c]);
    float sum = 0.f;
    #pragma unroll
    for (int c = 0; c < NC; c++) sum += expf(acc[c] - m);
    float l = logf(sum);
    #pragma unroll
    for (int c = 0; c < NC; c++) out[(size_t)b * NC + c] = acc[c] - m - l;
}

// ---------------- launch ----------------
#define GATHER_SMEM ((NN * 32 + NN) * sizeof(float))   // 66 KB

extern "C" void kernel_launch(void* const* d_in, const int* in_sizes, int n_in,
                              void* d_out, int out_size) {
    const float* x   = (const float*)d_in[0];
    const int*   ei  = (const int*)d_in[1];    // int32 (JAX x64 disabled)
    // d_in[2] = batch (unused; layout is implicit b*512+n)
    const float* W1  = (const float*)d_in[3];
    const float* b1  = (const float*)d_in[4];
    const float* W2  = (const float*)d_in[5];
    const float* b2  = (const float*)d_in[6];
    const float* pw  = (const float*)d_in[7];
    const float* fcW = (const float*)d_in[8];
    const float* fcb = (const float*)d_in[9];
    float*       out = (float*)d_out;

    static bool attr_done = false;
    if (!attr_done) {
        cudaFuncSetAttribute(k_gather_s<0>, cudaFuncAttributeMaxDynamicSharedMemorySize, GATHER_SMEM);
        cudaFuncSetAttribute(k_gather_s<1>, cudaFuncAttributeMaxDynamicSharedMemorySize, GATHER_SMEM);
        attr_done = true;
    }

    k_build<<<NB, NN>>>(ei);
    k_gemm1<<<NNODES / 32, dim3(16, 8)>>>(x, W1);
    k_gather_s<0><<<dim3(NB, 2), NN, GATHER_SMEM>>>(b1);
    k_gather_s<1><<<dim3(NB, 2), NN, GATHER_SMEM>>>(nullptr);
    k_gemm2<<<NNODES / 64, dim3(32, 8)>>>(W2, b2, pw);
    k_pool<<<NB, NN>>>();
    k_fc<<<1, NB>>>(fcW, fcb, out);
}

// round 6
// speedup vs baseline: 1.0112x; 1.0112x over previous
#include <cuda_runtime.h>
#include <cuda_bf16.h>

// Problem constants
#define NB 128          // graphs
#define NN 512          // nodes per graph
#define NNODES (NB*NN)  // 65536
#define NE 524288       // edges
#define EPG 4096        // edges per graph
#define EPT 8           // edges per thread in build (4096/512)
#define F_IN 128
#define H1 64
#define H2 128
#define NC 10
#define KSEL 410        // ceil(0.8*512)

// ---------------- scratch (static device globals; no allocation) ----------------
__device__ __align__(16) int            g_rowstart[NNODES];  // per-node excl. offset within graph
__device__ __align__(16) int            g_deg[NNODES];
__device__ __align__(16) unsigned short g_col16[NE];         // local src ids, grouped per graph
__device__ __align__(16) float          g_dis[NNODES];
__device__ __align__(16) float          g_h1[NNODES * H1];
__device__ __align__(16) float          g_out1[NNODES * H1];
__device__ __align__(16) float          g_a2[NNODES * H1];
__device__ __align__(16) float          g_out2[NNODES * H2];
__device__ __align__(16) float          g_score[NNODES];
__device__ __align__(16) float          g_gmax[NB * H2];

// ---------------- fused per-graph CSR build ----------------
// one block per graph, 512 threads; smem atomics + smem scan + smem-offset scatter
__global__ void k_build(const int* __restrict__ ei) {
    __shared__ int cnt[NN];
    __shared__ int scn[NN];
    __shared__ int fill[NN];
    int b = blockIdx.x, t = threadIdx.x;
    cnt[t] = 0;
    __syncthreads();

    int ebase = b * EPG;
    int sl[EPT], dl[EPT];
    #pragma unroll
    for (int j = 0; j < EPT; j++) {
        int e = ebase + j * NN + t;           // coalesced
        sl[j] = ei[e] & (NN - 1);             // local ids (graph offset removed by mask)
        dl[j] = ei[NE + e] & (NN - 1);
        atomicAdd(&cnt[dl[j]], 1);
    }
    __syncthreads();

    int c = cnt[t];
    scn[t] = c;
    __syncthreads();
    #pragma unroll
    for (int off = 1; off < NN; off <<= 1) {
        int v = (t >= off) ? scn[t - off] : 0;
        __syncthreads();
        scn[t] += v;
        __syncthreads();
    }
    int excl = scn[t] - c;
    int gv = b * NN + t;
    g_rowstart[gv] = excl;
    g_deg[gv] = c;
    g_dis[gv] = rsqrtf((float)(c + 1));       // +1 self loop
    fill[t] = excl;
    __syncthreads();

    #pragma unroll
    for (int j = 0; j < EPT; j++) {
        int pos = atomicAdd(&fill[dl[j]], 1);
        g_col16[ebase + pos] = (unsigned short)sl[j];
    }
}

// ---------------- GEMM1: g_h1[65536,64] = X[65536,128] @ W1[128,64] ----------------
__global__ void k_gemm1(const float* __restrict__ X, const float* __restrict__ W) {
    __shared__ float Ws[F_IN * H1];    // 32 KB
    __shared__ float Xs[32 * F_IN];    // 16 KB
    int tx = threadIdx.x, ty = threadIdx.y;
    int t = ty * 16 + tx;
    int row0 = blockIdx.x * 32;

    float4* Ws4 = (float4*)Ws;
    const float4* Wg = (const float4*)W;
    #pragma unroll
    for (int l = t; l < (F_IN * H1) / 4; l += 128) Ws4[l] = Wg[l];

    float4* Xs4 = (float4*)Xs;
    const float4* Xg = (const float4*)(X + (size_t)row0 * F_IN);
    #pragma unroll
    for (int l = t; l < (32 * F_IN) / 4; l += 128) Xs4[l] = Xg[l];
    __syncthreads();

    float acc[4][4];
    #pragma unroll
    for (int r = 0; r < 4; r++)
        #pragma unroll
        for (int c = 0; c < 4; c++) acc[r][c] = 0.f;

    #pragma unroll 4
    for (int k = 0; k < F_IN; k += 4) {
        float4 xq[4];
        #pragma unroll
        for (int r = 0; r < 4; r++) xq[r] = Xs4[(ty * 4 + r) * (F_IN / 4) + k / 4];
        #pragma unroll
        for (int kk = 0; kk < 4; kk++) {
            float4 w = Ws4[(k + kk) * (H1 / 4) + tx];
            #pragma unroll
            for (int r = 0; r < 4; r++) {
                float xv = (kk == 0) ? xq[r].x : (kk == 1) ? xq[r].y : (kk == 2) ? xq[r].z : xq[r].w;
                acc[r][0] += xv * w.x;
                acc[r][1] += xv * w.y;
                acc[r][2] += xv * w.z;
                acc[r][3] += xv * w.w;
            }
        }
    }
    #pragma unroll
    for (int r = 0; r < 4; r++) {
        float4 o = make_float4(acc[r][0], acc[r][1], acc[r][2], acc[r][3]);
        ((float4*)g_h1)[((size_t)(row0 + ty * 4 + r) * H1 + tx * 4) / 4] = o;
    }
}

// ---------------- smem-staged gather, one (graph, feature-half) per block ----------------
// PASS 0: g_out1 = relu( Agg(g_h1) + b1 );  PASS 1: g_a2 = Agg(g_out1)
// Agg(h)[v] = sum_{s in in(v)} dis[s]*dis[v]*h[s] + dis[v]^2 * h[v]
// smem: feats 64KB + dis 2KB + cols(u16) 8KB = 74KB -> 3 blocks/SM, grid 256 -> one wave
template <int PASS>
__global__ void k_gather_s(const float* __restrict__ bias) {
    extern __shared__ float smem[];
    float* hs   = smem;                                  // 512 nodes x 32 feats
    float* diss = smem + NN * 32;                        // 512 floats
    unsigned short* cols = (unsigned short*)(diss + NN); // 4096 u16
    const float* __restrict__ h   = (PASS == 0) ? g_h1   : g_out1;
    float* __restrict__       out = (PASS == 0) ? g_out1 : g_a2;

    int b = blockIdx.x, half = blockIdx.y, t = threadIdx.x;  // 512 threads
    int gbase = b * NN;

    // stage features: smem layout [node][32]; global row = 64 floats (16 float4)
    float4* hs4 = (float4*)hs;
    const float4* g4 = (const float4*)h;
    #pragma unroll
    for (int j = 0; j < 8; j++) {
        int f = j * NN + t;        // f = node*8 + q
        int node = f >> 3, q = f & 7;
        hs4[f] = g4[(size_t)(gbase + node) * 16 + half * 8 + q];
    }
    diss[t] = g_dis[gbase + t];
    // stage column indices (4096 u16 = 2048 u32)
    {
        const unsigned int* gc = (const unsigned int*)(g_col16 + b * EPG);
        unsigned int* sc = (unsigned int*)cols;
        #pragma unroll
        for (int j = 0; j < 4; j++) sc[j * NN + t] = gc[j * NN + t];
    }
    __syncthreads();

    int warp = t >> 5, lane = t & 31;
    #pragma unroll 1
    for (int v0 = warp * 2; v0 < NN; v0 += 32) {
        int v1 = v0 + 1;
        float dv0 = diss[v0], dv1 = diss[v1];
        int beg0 = g_rowstart[gbase + v0], d0 = g_deg[gbase + v0];
        int beg1 = g_rowstart[gbase + v1], d1 = g_deg[gbase + v1];
        float a0 = dv0 * dv0 * hs[v0 * 32 + lane];
        float a1 = dv1 * dv1 * hs[v1 * 32 + lane];
        int dmax = max(d0, d1);
        #pragma unroll 1
        for (int e = 0; e < dmax; e++) {
            if (e < d0) {
                int s = cols[beg0 + e];
                a0 = fmaf(dv0 * diss[s], hs[s * 32 + lane], a0);
            }
            if (e < d1) {
                int s = cols[beg1 + e];
                a1 = fmaf(dv1 * diss[s], hs[s * 32 + lane], a1);
            }
        }
        if (PASS == 0) {
            float bb = bias[half * 32 + lane];
            a0 = fmaxf(a0 + bb, 0.f);
            a1 = fmaxf(a1 + bb, 0.f);
        }
        out[(size_t)(gbase + v0) * H1 + half * 32 + lane] = a0;
        out[(size_t)(gbase + v1) * H1 + half * 32 + lane] = a1;
    }
}

// ---------------- GEMM2 + fused score: g_out2 = relu(g_a2 @ W2 + b2), g_score = out2.pw/||pw|| ----------------
// tile 64 rows x 128 cols, block (32,8)=256 thr; warp = fixed ty owns 8 full rows
__global__ void k_gemm2(const float* __restrict__ W, const float* __restrict__ bias,
                        const float* __restrict__ pw) {
    __shared__ float Ws[H1 * H2];   // 32 KB
    __shared__ float Xs[64 * H1];   // 16 KB
    int tx = threadIdx.x, ty = threadIdx.y;
    int t = ty * 32 + tx;
    int row0 = blockIdx.x * 64;

    float4* Ws4 = (float4*)Ws;
    const float4* Wg = (const float4*)W;
    #pragma unroll
    for (int l = t; l < (H1 * H2) / 4; l += 256) Ws4[l] = Wg[l];

    float4* Xs4 = (float4*)Xs;
    const float4* Ag = (const float4*)(g_a2 + (size_t)row0 * H1);
    #pragma unroll
    for (int l = t; l < (64 * H1) / 4; l += 256) Xs4[l] = Ag[l];
    __syncthreads();

    float acc[8][4];
    #pragma unroll
    for (int r = 0; r < 8; r++)
        #pragma unroll
        for (int c = 0; c < 4; c++) acc[r][c] = 0.f;

    #pragma unroll 2
    for (int k = 0; k < H1; k += 4) {
        float4 xq[8];
        #pragma unroll
        for (int r = 0; r < 8; r++) xq[r] = Xs4[(ty * 8 + r) * (H1 / 4) + k / 4];
        #pragma unroll
        for (int kk = 0; kk < 4; kk++) {
            float4 w = Ws4[(k + kk) * (H2 / 4) + tx];
            #pragma unroll
            for (int r = 0; r < 8; r++) {
                float xv = (kk == 0) ? xq[r].x : (kk == 1) ? xq[r].y : (kk == 2) ? xq[r].z : xq[r].w;
                acc[r][0] += xv * w.x;
                acc[r][1] += xv * w.y;
                acc[r][2] += xv * w.z;
                acc[r][3] += xv * w.w;
            }
        }
    }

    float4 bq = ((const float4*)bias)[tx];
    float4 p  = ((const float4*)pw)[tx];
    float nn = p.x * p.x + p.y * p.y + p.z * p.z + p.w * p.w;
    #pragma unroll
    for (int off = 16; off > 0; off >>= 1) nn += __shfl_xor_sync(0xffffffffu, nn, off);
    float rn = rsqrtf(nn);

    #pragma unroll
    for (int r = 0; r < 8; r++) {
        float4 o;
        o.x = fmaxf(acc[r][0] + bq.x, 0.f);
        o.y = fmaxf(acc[r][1] + bq.y, 0.f);
        o.z = fmaxf(acc[r][2] + bq.z, 0.f);
        o.w = fmaxf(acc[r][3] + bq.w, 0.f);
        int row = row0 + ty * 8 + r;
        ((float4*)g_out2)[((size_t)row * H2 + tx * 4) / 4] = o;
        float sp = o.x * p.x + o.y * p.y + o.z * p.z + o.w * p.w;
        #pragma unroll
        for (int off = 16; off > 0; off >>= 1) sp += __shfl_xor_sync(0xffffffffu, sp, off);
        if (tx == 0) g_score[row] = sp * rn;
    }
}

// ---------------- top-K selection + gated global max pool, one block per graph ----------------
__global__ void k_pool() {
    __shared__ float s[NN];
    __shared__ float gate[NN];
    __shared__ int   sel[NN];
    __shared__ float red[NN];
    int b = blockIdx.x;
    int t = threadIdx.x;           // 512 threads
    float v = g_score[(size_t)b * NN + t];
    s[t] = v;
    __syncthreads();
    int rank = 0;
    for (int j = 0; j < NN; j++) {
        float u = s[j];
        rank += (u > v) || (u == v && j < t);
    }
    sel[t] = (rank < KSEL);
    gate[t] = tanhf(v);
    __syncthreads();
    int f = t & 127, ch = t >> 7;  // 4 chunks of 128 nodes each
    float m = -INFINITY;
    const float* base = g_out2 + ((size_t)b * NN) * H2;
    for (int i = ch * 128; i < ch * 128 + 128; i++) {
        if (sel[i]) m = fmaxf(m, base[(size_t)i * H2 + f] * gate[i]);
    }
    red[t] = m;
    __syncthreads();
    if (ch == 0) {
        float mm = fmaxf(fmaxf(red[f], red[f + 128]), fmaxf(red[f + 256], red[f + 384]));
        g_gmax[(size_t)b * H2 + f] = mm;
    }
}

// ---------------- FC + log_softmax, one thread per graph ----------------
__global__ void k_fc(const float* __restrict__ fcW, const float* __restrict__ fcb,
                     float* __restrict__ out) {
    int b = threadIdx.x;   // 128
    float acc[NC];
    #pragma unroll
    for (int c = 0; c < NC; c++) acc[c] = fcb[c];
    for (int k = 0; k < H2; k++) {
        float gv = g_gmax[(size_t)b * H2 + k];
        #pragma unroll
        for (int c = 0; c < NC; c++) acc[c] += gv * fcW[k * NC + c];
    }
    float m = acc[0];
    #pragma unroll
    for (int c = 1; c < NC; c++) m = fmaxf(m, acc[c]);
    float sum = 0.f;
    #pragma unroll
    for (int c = 0; c < NC; c++) sum += expf(acc[c] - m);
    float l = logf(sum);
    #pragma unroll
    for (int c = 0; c < NC; c++) out[(size_t)b * NC + c] = acc[c] - m - l;
}

// ---------------- launch ----------------
#define GATHER_SMEM (NN * 32 * 4 + NN * 4 + EPG * 2)   // 75776 B

extern "C" void kernel_launch(void* const* d_in, const int* in_sizes, int n_in,
                              void* d_out, int out_size) {
    const float* x   = (const float*)d_in[0];
    const int*   ei  = (const int*)d_in[1];    // int32 (JAX x64 disabled)
    // d_in[2] = batch (unused; layout is implicit b*512+n)
    const float* W1  = (const float*)d_in[3];
    const float* b1  = (const float*)d_in[4];
    const float* W2  = (const float*)d_in[5];
    const float* b2  = (const float*)d_in[6];
    const float* pw  = (const float*)d_in[7];
    const float* fcW = (const float*)d_in[8];
    const float* fcb = (const float*)d_in[9];
    float*       out = (float*)d_out;

    static bool attr_done = false;
    if (!attr_done) {
        cudaFuncSetAttribute(k_gather_s<0>, cudaFuncAttributeMaxDynamicSharedMemorySize, GATHER_SMEM);
        cudaFuncSetAttribute(k_gather_s<1>, cudaFuncAttributeMaxDynamicSharedMemorySize, GATHER_SMEM);
        attr_done = true;
    }

    k_build<<<NB, NN>>>(ei);
    k_gemm1<<<NNODES / 32, dim3(16, 8)>>>(x, W1);
    k_gather_s<0><<<dim3(NB, 2), NN, GATHER_SMEM>>>(b1);
    k_gather_s<1><<<dim3(NB, 2), NN, GATHER_SMEM>>>(nullptr);
    k_gemm2<<<NNODES / 64, dim3(32, 8)>>>(W2, b2, pw);
    k_pool<<<NB, NN>>>();
    k_fc<<<1, NB>>>(fcW, fcb, out);
}

// round 9
// speedup vs baseline: 1.5293x; 1.5123x over previous
#include <cuda_runtime.h>
#include <cuda_bf16.h>

// Problem constants
#define NB 128          // graphs
#define NN 512          // nodes per graph
#define NNODES (NB*NN)  // 65536
#define NE 524288       // edges
#define EPG 4096        // edges per graph
#define EPT 8           // edges per thread in build (4096/512)
#define F_IN 128
#define H1 64
#define H2 128
#define NC 10
#define KSEL 410        // ceil(0.8*512)

// ---------------- scratch (static device globals; no allocation) ----------------
__device__ __align__(16) int            g_rowstart[NNODES];  // per-node excl. offset within graph
__device__ __align__(16) unsigned short g_col16[NE];         // local src ids, CSR order per graph
__device__ __align__(16) float          g_w[NE];             // per-edge weight dis[s]*dis[d]
__device__ __align__(16) float          g_dis[NNODES];
__device__ __align__(16) float          g_h1[NNODES * H1];
__device__ __align__(16) float          g_out1[NNODES * H1];
__device__ __align__(16) float          g_a2[NNODES * H1];
__device__ __align__(16) float          g_out2[NNODES * H2];
__device__ __align__(16) float          g_score[NNODES];
__device__ __align__(16) float          g_gmax[NB * H2];

// ---------------- fused per-graph CSR build (+ per-edge weights) ----------------
// one block per graph, 512 threads; smem atomics + smem scan + smem-offset scatter
__global__ void k_build(const int* __restrict__ ei) {
    __shared__ int   cnt[NN];
    __shared__ int   scn[NN];
    __shared__ int   fill[NN];
    __shared__ float sdis[NN];
    int b = blockIdx.x, t = threadIdx.x;
    cnt[t] = 0;
    __syncthreads();

    int ebase = b * EPG;
    int sl[EPT], dl[EPT];
    #pragma unroll
    for (int j = 0; j < EPT; j++) {
        int e = ebase + j * NN + t;           // coalesced
        sl[j] = ei[e] & (NN - 1);             // local ids (graph offset removed by mask)
        dl[j] = ei[NE + e] & (NN - 1);
        atomicAdd(&cnt[dl[j]], 1);
    }
    __syncthreads();

    int c = cnt[t];
    scn[t] = c;
    __syncthreads();
    #pragma unroll
    for (int off = 1; off < NN; off <<= 1) {
        int v = (t >= off) ? scn[t - off] : 0;
        __syncthreads();
        scn[t] += v;
        __syncthreads();
    }
    int excl = scn[t] - c;
    int gv = b * NN + t;
    float dv = rsqrtf((float)(c + 1));        // +1 self loop
    g_rowstart[gv] = excl;
    g_dis[gv] = dv;
    sdis[t] = dv;
    fill[t] = excl;
    __syncthreads();

    #pragma unroll
    for (int j = 0; j < EPT; j++) {
        int pos = atomicAdd(&fill[dl[j]], 1);
        g_col16[ebase + pos] = (unsigned short)sl[j];
        g_w[ebase + pos] = sdis[sl[j]] * sdis[dl[j]];
    }
}

// ---------------- GEMM1: g_h1[65536,64] = X[65536,128] @ W1[128,64] ----------------
__global__ void k_gemm1(const float* __restrict__ X, const float* __restrict__ W) {
    __shared__ float Ws[F_IN * H1];    // 32 KB
    __shared__ float Xs[32 * F_IN];    // 16 KB
    int tx = threadIdx.x, ty = threadIdx.y;
    int t = ty * 16 + tx;
    int row0 = blockIdx.x * 32;

    float4* Ws4 = (float4*)Ws;
    const float4* Wg = (const float4*)W;
    #pragma unroll
    for (int l = t; l < (F_IN * H1) / 4; l += 128) Ws4[l] = Wg[l];

    float4* Xs4 = (float4*)Xs;
    const float4* Xg = (const float4*)(X + (size_t)row0 * F_IN);
    #pragma unroll
    for (int l = t; l < (32 * F_IN) / 4; l += 128) Xs4[l] = Xg[l];
    __syncthreads();

    float acc[4][4];
    #pragma unroll
    for (int r = 0; r < 4; r++)
        #pragma unroll
        for (int c = 0; c < 4; c++) acc[r][c] = 0.f;

    #pragma unroll 4
    for (int k = 0; k < F_IN; k += 4) {
        float4 xq[4];
        #pragma unroll
        for (int r = 0; r < 4; r++) xq[r] = Xs4[(ty * 4 + r) * (F_IN / 4) + k / 4];
        #pragma unroll
        for (int kk = 0; kk < 4; kk++) {
            float4 w = Ws4[(k + kk) * (H1 / 4) + tx];
            #pragma unroll
            for (int r = 0; r < 4; r++) {
                float xv = (kk == 0) ? xq[r].x : (kk == 1) ? xq[r].y : (kk == 2) ? xq[r].z : xq[r].w;
                acc[r][0] += xv * w.x;
                acc[r][1] += xv * w.y;
                acc[r][2] += xv * w.z;
                acc[r][3] += xv * w.w;
            }
        }
    }
    #pragma unroll
    for (int r = 0; r < 4; r++) {
        float4 o = make_float4(acc[r][0], acc[r][1], acc[r][2], acc[r][3]);
        ((float4*)g_h1)[((size_t)(row0 + ty * 4 + r) * H1 + tx * 4) / 4] = o;
    }
}

// ---------------- smem-staged gather, one (graph, feature-half) per block ----------------
// PASS 0: g_out1 = relu( Agg(g_h1) + b1 );  PASS 1: g_a2 = Agg(g_out1)
// Agg(h)[v] = sum_e w_e * h[src_e] + dis[v]^2 * h[v]
// smem: feats 64KB + w 16KB + dis 2KB + rowstart 2KB + cols(u16) 8KB = 92KB -> 2 blocks/SM
template <int PASS>
__global__ void k_gather_s(const float* __restrict__ bias) {
    extern __shared__ float smem[];
    float* hs   = smem;                                   // NN*32 floats
    float* wts  = smem + NN * 32;                         // EPG floats
    float* diss = wts + EPG;                              // NN floats
    int*   rs   = (int*)(diss + NN);                      // NN+1 ints (+pad)
    unsigned short* cols = (unsigned short*)(rs + NN + 2); // EPG u16
    const float* __restrict__ h   = (PASS == 0) ? g_h1   : g_out1;
    float* __restrict__       out = (PASS == 0) ? g_out1 : g_a2;

    int b = blockIdx.x, half = blockIdx.y, t = threadIdx.x;  // 512 threads
    int gbase = b * NN;
    int ebase = b * EPG;

    // stage features: smem layout [node][32]; global row = 64 floats (16 float4)
    float4* hs4 = (float4*)hs;
    const float4* g4 = (const float4*)h;
    #pragma unroll
    for (int j = 0; j < 8; j++) {
        int f = j * NN + t;        // f = node*8 + q
        int node = f >> 3, q = f & 7;
        hs4[f] = g4[(size_t)(gbase + node) * 16 + half * 8 + q];
    }
    // stage edge weights (4096 floats = 1024 float4)
    {
        float4* sw4 = (float4*)wts;
        const float4* gw4 = (const float4*)(g_w + ebase);
        sw4[t] = gw4[t];
        sw4[NN + t] = gw4[NN + t];
    }
    // stage cols (4096 u16 = 2048 u32)
    {
        const unsigned int* gc = (const unsigned int*)(g_col16 + ebase);
        unsigned int* sc = (unsigned int*)cols;
        #pragma unroll
        for (int j = 0; j < 4; j++) sc[j * NN + t] = gc[j * NN + t];
    }
    diss[t] = g_dis[gbase + t];
    rs[t] = g_rowstart[gbase + t];
    if (t == 0) rs[NN] = EPG;      // every graph has exactly EPG edges
    __syncthreads();

    int warp = t >> 5, lane = t & 31;
    int v0 = warp * 32, v1 = v0 + 32;   // contiguous node range per warp
    float bb = (PASS == 0) ? bias[half * 32 + lane] : 0.f;
    #pragma unroll 1
    for (int v = v0; v < v1; v++) {
        float dv = diss[v];
        int beg = rs[v], end = rs[v + 1];
        float a = dv * dv * hs[v * 32 + lane];
        #pragma unroll 4
        for (int e = beg; e < end; e++) {
            int s = cols[e];
            a = fmaf(wts[e], hs[s * 32 + lane], a);
        }
        if (PASS == 0) a = fmaxf(a + bb, 0.f);
        out[(size_t)(gbase + v) * H1 + half * 32 + lane] = a;
    }
}

// ---------------- GEMM2 + fused score: g_out2 = relu(g_a2 @ W2 + b2), g_score = out2.pw/||pw|| ----------------
// tile 64 rows x 128 cols, block (32,8)=256 thr; warp = fixed ty owns 8 full rows
__global__ void k_gemm2(const float* __restrict__ W, const float* __restrict__ bias,
                        const float* __restrict__ pw) {
    __shared__ float Ws[H1 * H2];   // 32 KB
    __shared__ float Xs[64 * H1];   // 16 KB
    int tx = threadIdx.x, ty = threadIdx.y;
    int t = ty * 32 + tx;
    int row0 = blockIdx.x * 64;

    float4* Ws4 = (float4*)Ws;
    const float4* Wg = (const float4*)W;
    #pragma unroll
    for (int l = t; l < (H1 * H2) / 4; l += 256) Ws4[l] = Wg[l];

    float4* Xs4 = (float4*)Xs;
    const float4* Ag = (const float4*)(g_a2 + (size_t)row0 * H1);
    #pragma unroll
    for (int l = t; l < (64 * H1) / 4; l += 256) Xs4[l] = Ag[l];
    __syncthreads();

    float acc[8][4];
    #pragma unroll
    for (int r = 0; r < 8; r++)
        #pragma unroll
        for (int c = 0; c < 4; c++) acc[r][c] = 0.f;

    #pragma unroll 2
    for (int k = 0; k < H1; k += 4) {
        float4 xq[8];
        #pragma unroll
        for (int r = 0; r < 8; r++) xq[r] = Xs4[(ty * 8 + r) * (H1 / 4) + k / 4];
        #pragma unroll
        for (int kk = 0; kk < 4; kk++) {
            float4 w = Ws4[(k + kk) * (H2 / 4) + tx];
            #pragma unroll
            for (int r = 0; r < 8; r++) {
                float xv = (kk == 0) ? xq[r].x : (kk == 1) ? xq[r].y : (kk == 2) ? xq[r].z : xq[r].w;
                acc[r][0] += xv * w.x;
                acc[r][1] += xv * w.y;
                acc[r][2] += xv * w.z;
                acc[r][3] += xv * w.w;
            }
        }
    }

    float4 bq = ((const float4*)bias)[tx];
    float4 p  = ((const float4*)pw)[tx];
    float nn = p.x * p.x + p.y * p.y + p.z * p.z + p.w * p.w;
    #pragma unroll
    for (int off = 16; off > 0; off >>= 1) nn += __shfl_xor_sync(0xffffffffu, nn, off);
    float rn = rsqrtf(nn);

    #pragma unroll
    for (int r = 0; r < 8; r++) {
        float4 o;
        o.x = fmaxf(acc[r][0] + bq.x, 0.f);
        o.y = fmaxf(acc[r][1] + bq.y, 0.f);
        o.z = fmaxf(acc[r][2] + bq.z, 0.f);
        o.w = fmaxf(acc[r][3] + bq.w, 0.f);
        int row = row0 + ty * 8 + r;
        ((float4*)g_out2)[((size_t)row * H2 + tx * 4) / 4] = o;
        float sp = o.x * p.x + o.y * p.y + o.z * p.z + o.w * p.w;
        #pragma unroll
        for (int off = 16; off > 0; off >>= 1) sp += __shfl_xor_sync(0xffffffffu, sp, off);
        if (tx == 0) g_score[row] = sp * rn;
    }
}

// ---------------- top-K selection + gated global max pool, one block per graph ----------------
__global__ void k_pool() {
    __shared__ float s[NN];
    __shared__ float gate[NN];
    __shared__ int   sel[NN];
    __shared__ float red[NN];
    int b = blockIdx.x;
    int t = threadIdx.x;           // 512 threads
    float v = g_score[(size_t)b * NN + t];
    s[t] = v;
    __syncthreads();
    int rank = 0;
    for (int j = 0; j < NN; j++) {
        float u = s[j];
        rank += (u > v) || (u == v && j < t);
    }
    sel[t] = (rank < KSEL);
    gate[t] = tanhf(v);
    __syncthreads();
    int f = t & 127, ch = t >> 7;  // 4 chunks of 128 nodes each
    float m = -INFINITY;
    const float* base = g_out2 + ((size_t)b * NN) * H2;
    for (int i = ch * 128; i < ch * 128 + 128; i++) {
        if (sel[i]) m = fmaxf(m, base[(size_t)i * H2 + f] * gate[i]);
    }
    red[t] = m;
    __syncthreads();
    if (ch == 0) {
        float mm = fmaxf(fmaxf(red[f], red[f + 128]), fmaxf(red[f + 256], red[f + 384]));
        g_gmax[(size_t)b * H2 + f] = mm;
    }
}

// ---------------- FC + log_softmax, one thread per graph ----------------
__global__ void k_fc(const float* __restrict__ fcW, const float* __restrict__ fcb,
                     float* __restrict__ out) {
    int b = threadIdx.x;   // 128
    float acc[NC];
    #pragma unroll
    for (int c = 0; c < NC; c++) acc[c] = fcb[c];
    for (int k = 0; k < H2; k++) {
        float gv = g_gmax[(size_t)b * H2 + k];
        #pragma unroll
        for (int c = 0; c < NC; c++) acc[c] += gv * fcW[k * NC + c];
    }
    float m = acc[0];
    #pragma unroll
    for (int c = 1; c < NC; c++) m = fmaxf(m, acc[c]);
    float sum = 0.f;
    #pragma unroll
    for (int c = 0; c < NC; c++) sum += expf(acc[c] - m);
    float l = logf(sum);
    #pragma unroll
    for (int c = 0; c < NC; c++) out[(size_t)b * NC + c] = acc[c] - m - l;
}

// ---------------- launch ----------------
// hs 64KB + wts 16KB + dis 2KB + rs (NN+2)*4 + cols 8KB
#define GATHER_SMEM (NN*32*4 + EPG*4 + NN*4 + (NN+2)*4 + EPG*2)

extern "C" void kernel_launch(void* const* d_in, const int* in_sizes, int n_in,
                              void* d_out, int out_size) {
    const float* x   = (const float*)d_in[0];
    const int*   ei  = (const int*)d_in[1];    // int32 (JAX x64 disabled)
    // d_in[2] = batch (unused; layout is implicit b*512+n)
    const float* W1  = (const float*)d_in[3];
    const float* b1  = (const float*)d_in[4];
    const float* W2  = (const float*)d_in[5];
    const float* b2  = (const float*)d_in[6];
    const float* pw  = (const float*)d_in[7];
    const float* fcW = (const float*)d_in[8];
    const float* fcb = (const float*)d_in[9];
    float*       out = (float*)d_out;

    static bool attr_done = false;
    if (!attr_done) {
        cudaFuncSetAttribute(k_gather_s<0>, cudaFuncAttributeMaxDynamicSharedMemorySize, GATHER_SMEM);
        cudaFuncSetAttribute(k_gather_s<1>, cudaFuncAttributeMaxDynamicSharedMemorySize, GATHER_SMEM);
        attr_done = true;
    }

    k_build<<<NB, NN>>>(ei);
    k_gemm1<<<NNODES / 32, dim3(16, 8)>>>(x, W1);
    k_gather_s<0><<<dim3(NB, 2), NN, GATHER_SMEM>>>(b1);
    k_gather_s<1><<<dim3(NB, 2), NN, GATHER_SMEM>>>(nullptr);
    k_gemm2<<<NNODES / 64, dim3(32, 8)>>>(W2, b2, pw);
    k_pool<<<NB, NN>>>();
    k_fc<<<1, NB>>>(fcW, fcb, out);
}

// round 12
// speedup vs baseline: 1.5629x; 1.0220x over previous
#include <cuda_runtime.h>
#include <cuda_bf16.h>

// Problem constants
#define NB 128          // graphs
#define NN 512          // nodes per graph
#define NNODES (NB*NN)  // 65536
#define NE 524288       // edges
#define EPG 4096        // edges per graph
#define EPT 8           // edges per thread in build (4096/512)
#define F_IN 128
#define H1 64
#define H2 128
#define NC 10
#define KSEL 410        // ceil(0.8*512)

// ---------------- scratch (static device globals; no allocation) ----------------
__device__ __align__(16) int            g_rowstart[NNODES];  // per-node excl. offset within graph
__device__ __align__(16) unsigned short g_col16[NE];         // local src ids, CSR order per graph
__device__ __align__(16) float          g_dis[NNODES];
__device__ __align__(16) float          g_h1[NNODES * H1];
__device__ __align__(16) float          g_out1[NNODES * H1];
__device__ __align__(16) float          g_a2[NNODES * H1];
__device__ __align__(16) float          g_out2[NNODES * H2];
__device__ __align__(16) float          g_score[NNODES];
__device__ __align__(16) float          g_gmax[NB * H2];

// ---------------- fused per-graph CSR build ----------------
// one block per graph, 512 threads; smem atomics + smem scan + smem-offset scatter
__global__ void k_build(const int* __restrict__ ei) {
    __shared__ int cnt[NN];
    __shared__ int scn[NN];
    __shared__ int fill[NN];
    int b = blockIdx.x, t = threadIdx.x;
    cnt[t] = 0;
    __syncthreads();

    int ebase = b * EPG;
    int sl[EPT], dl[EPT];
    #pragma unroll
    for (int j = 0; j < EPT; j++) {
        int e = ebase + j * NN + t;           // coalesced
        sl[j] = ei[e] & (NN - 1);             // local ids (graph offset removed by mask)
        dl[j] = ei[NE + e] & (NN - 1);
        atomicAdd(&cnt[dl[j]], 1);
    }
    __syncthreads();

    int c = cnt[t];
    scn[t] = c;
    __syncthreads();
    #pragma unroll
    for (int off = 1; off < NN; off <<= 1) {
        int v = (t >= off) ? scn[t - off] : 0;
        __syncthreads();
        scn[t] += v;
        __syncthreads();
    }
    int excl = scn[t] - c;
    int gv = b * NN + t;
    g_rowstart[gv] = excl;
    g_dis[gv] = rsqrtf((float)(c + 1));       // +1 self loop
    fill[t] = excl;
    __syncthreads();

    #pragma unroll
    for (int j = 0; j < EPT; j++) {
        int pos = atomicAdd(&fill[dl[j]], 1);
        g_col16[ebase + pos] = (unsigned short)sl[j];
    }
}

// ---------------- GEMM1: g_h1[65536,64] = X[65536,128] @ W1[128,64] ----------------
__global__ void k_gemm1(const float* __restrict__ X, const float* __restrict__ W) {
    __shared__ float Ws[F_IN * H1];    // 32 KB
    __shared__ float Xs[32 * F_IN];    // 16 KB
    int tx = threadIdx.x, ty = threadIdx.y;
    int t = ty * 16 + tx;
    int row0 = blockIdx.x * 32;

    float4* Ws4 = (float4*)Ws;
    const float4* Wg = (const float4*)W;
    #pragma unroll
    for (int l = t; l < (F_IN * H1) / 4; l += 128) Ws4[l] = Wg[l];

    float4* Xs4 = (float4*)Xs;
    const float4* Xg = (const float4*)(X + (size_t)row0 * F_IN);
    #pragma unroll
    for (int l = t; l < (32 * F_IN) / 4; l += 128) Xs4[l] = Xg[l];
    __syncthreads();

    float acc[4][4];
    #pragma unroll
    for (int r = 0; r < 4; r++)
        #pragma unroll
        for (int c = 0; c < 4; c++) acc[r][c] = 0.f;

    #pragma unroll 4
    for (int k = 0; k < F_IN; k += 4) {
        float4 xq[4];
        #pragma unroll
        for (int r = 0; r < 4; r++) xq[r] = Xs4[(ty * 4 + r) * (F_IN / 4) + k / 4];
        #pragma unroll
        for (int kk = 0; kk < 4; kk++) {
            float4 w = Ws4[(k + kk) * (H1 / 4) + tx];
            #pragma unroll
            for (int r = 0; r < 4; r++) {
                float xv = (kk == 0) ? xq[r].x : (kk == 1) ? xq[r].y : (kk == 2) ? xq[r].z : xq[r].w;
                acc[r][0] += xv * w.x;
                acc[r][1] += xv * w.y;
                acc[r][2] += xv * w.z;
                acc[r][3] += xv * w.w;
            }
        }
    }
    #pragma unroll
    for (int r = 0; r < 4; r++) {
        float4 o = make_float4(acc[r][0], acc[r][1], acc[r][2], acc[r][3]);
        ((float4*)g_h1)[((size_t)(row0 + ty * 4 + r) * H1 + tx * 4) / 4] = o;
    }
}

// ---------------- smem-staged gather, one (graph, feature-half) per block ----------------
// PASS 0: g_out1 = relu( Agg(g_h1) + b1 );  PASS 1: g_a2 = Agg(g_out1)
// With hs'[i] = dis[i]*h[i]:  Agg(h)[v] = dis[v] * ( hs'[v] + sum_e hs'[col[e]] )
// smem: feats 64KB + dis 2KB + rowstart ~2KB + cols(u16) 8KB = 76KB -> 3 blocks/SM
template <int PASS>
__global__ void k_gather_s(const float* __restrict__ bias) {
    extern __shared__ float smem[];
    float* hs   = smem;                                   // NN*32 floats (pre-scaled by dis)
    float* diss = smem + NN * 32;                         // NN floats
    int*   rs   = (int*)(diss + NN);                      // NN+1 ints (+pad)
    unsigned short* cols = (unsigned short*)(rs + NN + 2); // EPG u16
    const float* __restrict__ h   = (PASS == 0) ? g_h1   : g_out1;
    float* __restrict__       out = (PASS == 0) ? g_out1 : g_a2;

    int b = blockIdx.x, half = blockIdx.y, t = threadIdx.x;  // 512 threads
    int gbase = b * NN;
    int ebase = b * EPG;

    diss[t] = g_dis[gbase + t];
    // stage cols (4096 u16 = 2048 u32)
    {
        const unsigned int* gc = (const unsigned int*)(g_col16 + ebase);
        unsigned int* sc = (unsigned int*)cols;
        #pragma unroll
        for (int j = 0; j < 4; j++) sc[j * NN + t] = gc[j * NN + t];
    }
    rs[t] = g_rowstart[gbase + t];
    if (t == 0) rs[NN] = EPG;      // every graph has exactly EPG edges
    __syncthreads();               // diss ready before pre-scaled staging

    // stage features pre-scaled: smem layout [node][32]; global row = 64 floats (16 float4)
    float4* hs4 = (float4*)hs;
    const float4* g4 = (const float4*)h;
    #pragma unroll
    for (int j = 0; j < 8; j++) {
        int f = j * NN + t;        // f = node*8 + q
        int node = f >> 3, q = f & 7;
        float dn = diss[node];
        float4 v = g4[(size_t)(gbase + node) * 16 + half * 8 + q];
        v.x *= dn; v.y *= dn; v.z *= dn; v.w *= dn;
        hs4[f] = v;
    }
    __syncthreads();

    int warp = t >> 5, lane = t & 31;
    int v0 = warp * 32, v1 = v0 + 32;   // contiguous node range per warp
    float bb = (PASS == 0) ? bias[half * 32 + lane] : 0.f;
    #pragma unroll 1
    for (int v = v0; v < v1; v++) {
        int beg = rs[v], end = rs[v + 1];
        float a0 = hs[v * 32 + lane];   // self term (pre-scaled)
        float a1 = 0.f;
        int e = beg;
        #pragma unroll 4
        for (; e + 2 <= end; e += 2) {
            int s0 = cols[e], s1 = cols[e + 1];
            a0 += hs[s0 * 32 + lane];
            a1 += hs[s1 * 32 + lane];
        }
        if (e < end) a0 += hs[cols[e] * 32 + lane];
        float a = diss[v] * (a0 + a1);
        if (PASS == 0) a = fmaxf(a + bb, 0.f);
        out[(size_t)(gbase + v) * H1 + half * 32 + lane] = a;
    }
}

// ---------------- GEMM2 + fused score: g_out2 = relu(g_a2 @ W2 + b2), g_score = out2.pw/||pw|| ----------------
// tile 64 rows x 128 cols, block (32,8)=256 thr; warp = fixed ty owns 8 full rows
__global__ void k_gemm2(const float* __restrict__ W, const float* __restrict__ bias,
                        const float* __restrict__ pw) {
    __shared__ float Ws[H1 * H2];   // 32 KB
    __shared__ float Xs[64 * H1];   // 16 KB
    int tx = threadIdx.x, ty = threadIdx.y;
    int t = ty * 32 + tx;
    int row0 = blockIdx.x * 64;

    float4* Ws4 = (float4*)Ws;
    const float4* Wg = (const float4*)W;
    #pragma unroll
    for (int l = t; l < (H1 * H2) / 4; l += 256) Ws4[l] = Wg[l];

    float4* Xs4 = (float4*)Xs;
    const float4* Ag = (const float4*)(g_a2 + (size_t)row0 * H1);
    #pragma unroll
    for (int l = t; l < (64 * H1) / 4; l += 256) Xs4[l] = Ag[l];
    __syncthreads();

    float acc[8][4];
    #pragma unroll
    for (int r = 0; r < 8; r++)
        #pragma unroll
        for (int c = 0; c < 4; c++) acc[r][c] = 0.f;

    #pragma unroll 2
    for (int k = 0; k < H1; k += 4) {
        float4 xq[8];
        #pragma unroll
        for (int r = 0; r < 8; r++) xq[r] = Xs4[(ty * 8 + r) * (H1 / 4) + k / 4];
        #pragma unroll
        for (int kk = 0; kk < 4; kk++) {
            float4 w = Ws4[(k + kk) * (H2 / 4) + tx];
            #pragma unroll
            for (int r = 0; r < 8; r++) {
                float xv = (kk == 0) ? xq[r].x : (kk == 1) ? xq[r].y : (kk == 2) ? xq[r].z : xq[r].w;
                acc[r][0] += xv * w.x;
                acc[r][1] += xv * w.y;
                acc[r][2] += xv * w.z;
                acc[r][3] += xv * w.w;
            }
        }
    }

    float4 bq = ((const float4*)bias)[tx];
    float4 p  = ((const float4*)pw)[tx];
    float nn = p.x * p.x + p.y * p.y + p.z * p.z + p.w * p.w;
    #pragma unroll
    for (int off = 16; off > 0; off >>= 1) nn += __shfl_xor_sync(0xffffffffu, nn, off);
    float rn = rsqrtf(nn);

    #pragma unroll
    for (int r = 0; r < 8; r++) {
        float4 o;
        o.x = fmaxf(acc[r][0] + bq.x, 0.f);
        o.y = fmaxf(acc[r][1] + bq.y, 0.f);
        o.z = fmaxf(acc[r][2] + bq.z, 0.f);
        o.w = fmaxf(acc[r][3] + bq.w, 0.f);
        int row = row0 + ty * 8 + r;
        ((float4*)g_out2)[((size_t)row * H2 + tx * 4) / 4] = o;
        float sp = o.x * p.x + o.y * p.y + o.z * p.z + o.w * p.w;
        #pragma unroll
        for (int off = 16; off > 0; off >>= 1) sp += __shfl_xor_sync(0xffffffffu, sp, off);
        if (tx == 0) g_score[row] = sp * rn;
    }
}

// ---------------- top-K selection + gated global max pool, one block per graph ----------------
__global__ void k_pool() {
    __shared__ float s[NN];
    __shared__ float gate[NN];
    __shared__ int   sel[NN];
    __shared__ float red[NN];
    int b = blockIdx.x;
    int t = threadIdx.x;           // 512 threads
    float v = g_score[(size_t)b * NN + t];
    s[t] = v;
    __syncthreads();
    int rank = 0;
    for (int j = 0; j < NN; j++) {
        float u = s[j];
        rank += (u > v) || (u == v && j < t);
    }
    sel[t] = (rank < KSEL);
    gate[t] = tanhf(v);
    __syncthreads();
    int f = t & 127, ch = t >> 7;  // 4 chunks of 128 nodes each
    float m = -INFINITY;
    const float* base = g_out2 + ((size_t)b * NN) * H2;
    for (int i = ch * 128; i < ch * 128 + 128; i++) {
        if (sel[i]) m = fmaxf(m, base[(size_t)i * H2 + f] * gate[i]);
    }
    red[t] = m;
    __syncthreads();
    if (ch == 0) {
        float mm = fmaxf(fmaxf(red[f], red[f + 128]), fmaxf(red[f + 256], red[f + 384]));
        g_gmax[(size_t)b * H2 + f] = mm;
    }
}

// ---------------- FC + log_softmax, one thread per graph ----------------
__global__ void k_fc(const float* __restrict__ fcW, const float* __restrict__ fcb,
                     float* __restrict__ out) {
    int b = threadIdx.x;   // 128
    float acc[NC];
    #pragma unroll
    for (int c = 0; c < NC; c++) acc[c] = fcb[c];
    for (int k = 0; k < H2; k++) {
        float gv = g_gmax[(size_t)b * H2 + k];
        #pragma unroll
        for (int c = 0; c < NC; c++) acc[c] += gv * fcW[k * NC + c];
    }
    float m = acc[0];
    #pragma unroll
    for (int c = 1; c < NC; c++) m = fmaxf(m, acc[c]);
    float sum = 0.f;
    #pragma unroll
    for (int c = 0; c < NC; c++) sum += expf(acc[c] - m);
    float l = logf(sum);
    #pragma unroll
    for (int c = 0; c < NC; c++) out[(size_t)b * NC + c] = acc[c] - m - l;
}

// ---------------- launch ----------------
// hs 64KB + dis 2KB + rs (NN+2)*4 + cols 8KB  = ~76KB -> 3 blocks/SM
#define GATHER_SMEM (NN*32*4 + NN*4 + (NN+2)*4 + EPG*2)

extern "C" void kernel_launch(void* const* d_in, const int* in_sizes, int n_in,
                              void* d_out, int out_size) {
    const float* x   = (const float*)d_in[0];
    const int*   ei  = (const int*)d_in[1];    // int32 (JAX x64 disabled)
    // d_in[2] = batch (unused; layout is implicit b*512+n)
    const float* W1  = (const float*)d_in[3];
    const float* b1  = (const float*)d_in[4];
    const float* W2  = (const float*)d_in[5];
    const float* b2  = (const float*)d_in[6];
    const float* pw  = (const float*)d_in[7];
    const float* fcW = (const float*)d_in[8];
    const float* fcb = (const float*)d_in[9];
    float*       out = (float*)d_out;

    static bool attr_done = false;
    if (!attr_done) {
        cudaFuncSetAttribute(k_gather_s<0>, cudaFuncAttributeMaxDynamicSharedMemorySize, GATHER_SMEM);
        cudaFuncSetAttribute(k_gather_s<1>, cudaFuncAttributeMaxDynamicSharedMemorySize, GATHER_SMEM);
        attr_done = true;
    }

    k_build<<<NB, NN>>>(ei);
    k_gemm1<<<NNODES / 32, dim3(16, 8)>>>(x, W1);
    k_gather_s<0><<<dim3(NB, 2), NN, GATHER_SMEM>>>(b1);
    k_gather_s<1><<<dim3(NB, 2), NN, GATHER_SMEM>>>(nullptr);
    k_gemm2<<<NNODES / 64, dim3(32, 8)>>>(W2, b2, pw);
    k_pool<<<NB, NN>>>();
    k_fc<<<1, NB>>>(fcW, fcb, out);
}

// round 14
// speedup vs baseline: 1.8183x; 1.1634x over previous
#include <cuda_runtime.h>
#include <cuda_bf16.h>

// Problem constants
#define NB 128          // graphs
#define NN 512          // nodes per graph
#define NNODES (NB*NN)  // 65536
#define NE 524288       // edges
#define EPG 4096        // edges per graph
#define EPT 8           // edges per thread in build (4096/512)
#define F_IN 128
#define H1 64
#define H2 128
#define NC 10
#define KSEL 410        // ceil(0.8*512)

// ---------------- scratch (static device globals; no allocation) ----------------
__device__ __align__(16) int            g_rowstart[NNODES];  // per-node excl. offset within graph
__device__ __align__(16) unsigned short g_col16[NE];         // local src ids, CSR order per graph
__device__ __align__(16) float          g_dis[NNODES];
__device__ __align__(16) float          g_h1[NNODES * H1];
__device__ __align__(16) float          g_out1[NNODES * H1];
__device__ __align__(16) float          g_a2[NNODES * H1];
__device__ __align__(16) float          g_out2[NNODES * H2];
__device__ __align__(16) float          g_score[NNODES];

// ---------------- fused per-graph CSR build ----------------
// one block per graph, 512 threads; smem atomics + smem scan + smem-offset scatter
__global__ void k_build(const int* __restrict__ ei) {
    __shared__ int cnt[NN];
    __shared__ int scn[NN];
    __shared__ int fill[NN];
    int b = blockIdx.x, t = threadIdx.x;
    cnt[t] = 0;
    __syncthreads();

    int ebase = b * EPG;
    int sl[EPT], dl[EPT];
    #pragma unroll
    for (int j = 0; j < EPT; j++) {
        int e = ebase + j * NN + t;           // coalesced
        sl[j] = ei[e] & (NN - 1);             // local ids (graph offset removed by mask)
        dl[j] = ei[NE + e] & (NN - 1);
        atomicAdd(&cnt[dl[j]], 1);
    }
    __syncthreads();

    int c = cnt[t];
    scn[t] = c;
    __syncthreads();
    #pragma unroll
    for (int off = 1; off < NN; off <<= 1) {
        int v = (t >= off) ? scn[t - off] : 0;
        __syncthreads();
        scn[t] += v;
        __syncthreads();
    }
    int excl = scn[t] - c;
    int gv = b * NN + t;
    g_rowstart[gv] = excl;
    g_dis[gv] = rsqrtf((float)(c + 1));       // +1 self loop
    fill[t] = excl;
    __syncthreads();

    #pragma unroll
    for (int j = 0; j < EPT; j++) {
        int pos = atomicAdd(&fill[dl[j]], 1);
        g_col16[ebase + pos] = (unsigned short)sl[j];
    }
}

// ---------------- GEMM1: g_h1[65536,64] = X[65536,128] @ W1[128,64] ----------------
__global__ void k_gemm1(const float* __restrict__ X, const float* __restrict__ W) {
    __shared__ float Ws[F_IN * H1];    // 32 KB
    __shared__ float Xs[32 * F_IN];    // 16 KB
    int tx = threadIdx.x, ty = threadIdx.y;
    int t = ty * 16 + tx;
    int row0 = blockIdx.x * 32;

    float4* Ws4 = (float4*)Ws;
    const float4* Wg = (const float4*)W;
    #pragma unroll
    for (int l = t; l < (F_IN * H1) / 4; l += 128) Ws4[l] = Wg[l];

    float4* Xs4 = (float4*)Xs;
    const float4* Xg = (const float4*)(X + (size_t)row0 * F_IN);
    #pragma unroll
    for (int l = t; l < (32 * F_IN) / 4; l += 128) Xs4[l] = Xg[l];
    __syncthreads();

    float acc[4][4];
    #pragma unroll
    for (int r = 0; r < 4; r++)
        #pragma unroll
        for (int c = 0; c < 4; c++) acc[r][c] = 0.f;

    #pragma unroll 4
    for (int k = 0; k < F_IN; k += 4) {
        float4 xq[4];
        #pragma unroll
        for (int r = 0; r < 4; r++) xq[r] = Xs4[(ty * 4 + r) * (F_IN / 4) + k / 4];
        #pragma unroll
        for (int kk = 0; kk < 4; kk++) {
            float4 w = Ws4[(k + kk) * (H1 / 4) + tx];
            #pragma unroll
            for (int r = 0; r < 4; r++) {
                float xv = (kk == 0) ? xq[r].x : (kk == 1) ? xq[r].y : (kk == 2) ? xq[r].z : xq[r].w;
                acc[r][0] += xv * w.x;
                acc[r][1] += xv * w.y;
                acc[r][2] += xv * w.z;
                acc[r][3] += xv * w.w;
            }
        }
    }
    #pragma unroll
    for (int r = 0; r < 4; r++) {
        float4 o = make_float4(acc[r][0], acc[r][1], acc[r][2], acc[r][3]);
        ((float4*)g_h1)[((size_t)(row0 + ty * 4 + r) * H1 + tx * 4) / 4] = o;
    }
}

// ---------------- smem-staged gather, one (graph, feature-half) per block ----------------
// PASS 0: g_out1 = relu( Agg(g_h1) + b1 );  PASS 1: g_a2 = Agg(g_out1)
// With hs'[i] = dis[i]*h[i]:  Agg(h)[v] = dis[v] * ( hs'[v] + sum_e hs'[col[e]] )
// smem: hs 64KB + rs 2052B + cols 8KB = 75780B <= 77824 -> 3 blocks/SM
template <int PASS>
__global__ void k_gather_s(const float* __restrict__ bias) {
    extern __shared__ float smem[];
    float* hs = smem;                                     // NN*32 floats (pre-scaled by dis)
    int*   rs = (int*)(smem + NN * 32);                   // NN+1 ints
    unsigned short* cols = (unsigned short*)(rs + NN + 1); // EPG u16 (offset 67588, 4B-aligned)
    const float* __restrict__ h   = (PASS == 0) ? g_h1   : g_out1;
    float* __restrict__       out = (PASS == 0) ? g_out1 : g_a2;

    int b = blockIdx.x, half = blockIdx.y, t = threadIdx.x;  // 512 threads
    int gbase = b * NN;
    int ebase = b * EPG;

    // stage cols (4096 u16 = 2048 u32)
    {
        const unsigned int* gc = (const unsigned int*)(g_col16 + ebase);
        unsigned int* sc = (unsigned int*)cols;
        #pragma unroll
        for (int j = 0; j < 4; j++) sc[j * NN + t] = gc[j * NN + t];
    }
    rs[t] = g_rowstart[gbase + t];
    if (t == 0) rs[NN] = EPG;      // every graph has exactly EPG edges

    // stage features pre-scaled by dis: smem layout [node][32]
    float4* hs4 = (float4*)hs;
    const float4* g4 = (const float4*)h;
    #pragma unroll
    for (int j = 0; j < 8; j++) {
        int f = j * NN + t;        // f = node*8 + q
        int node = f >> 3, q = f & 7;
        float dn = g_dis[gbase + node];     // L1-resident broadcast
        float4 v = g4[(size_t)(gbase + node) * 16 + half * 8 + q];
        v.x *= dn; v.y *= dn; v.z *= dn; v.w *= dn;
        hs4[f] = v;
    }
    __syncthreads();

    int warp = t >> 5, lane = t & 31;
    int v0 = warp * 32;                      // contiguous node range per warp
    float dvreg = g_dis[gbase + v0 + lane];  // per-lane dis, broadcast by shfl below
    float bb = (PASS == 0) ? bias[half * 32 + lane] : 0.f;
    const float* hl = hs + lane;
    #pragma unroll 1
    for (int i = 0; i < 32; i++) {
        int v = v0 + i;
        int beg = rs[v], end = rs[v + 1];
        float dv = __shfl_sync(0xffffffffu, dvreg, i);
        float a0 = hl[v * 32];               // self term (pre-scaled)
        float a1 = 0.f;
        int e = beg;
        #pragma unroll 4
        for (; e + 2 <= end; e += 2) {
            int s0 = cols[e], s1 = cols[e + 1];
            a0 += hl[s0 * 32];
            a1 += hl[s1 * 32];
        }
        if (e < end) a0 += hl[cols[e] * 32];
        float a = dv * (a0 + a1);
        if (PASS == 0) a = fmaxf(a + bb, 0.f);
        out[(size_t)(gbase + v) * H1 + half * 32 + lane] = a;
    }
}

// ---------------- GEMM2 + fused score: g_out2 = relu(g_a2 @ W2 + b2), g_score = out2.pw/||pw|| ----------------
// tile 64 rows x 128 cols, block (32,8)=256 thr; warp = fixed ty owns 8 full rows
__global__ void k_gemm2(const float* __restrict__ W, const float* __restrict__ bias,
                        const float* __restrict__ pw) {
    __shared__ float Ws[H1 * H2];   // 32 KB
    __shared__ float Xs[64 * H1];   // 16 KB
    int tx = threadIdx.x, ty = threadIdx.y;
    int t = ty * 32 + tx;
    int row0 = blockIdx.x * 64;

    float4* Ws4 = (float4*)Ws;
    const float4* Wg = (const float4*)W;
    #pragma unroll
    for (int l = t; l < (H1 * H2) / 4; l += 256) Ws4[l] = Wg[l];

    float4* Xs4 = (float4*)Xs;
    const float4* Ag = (const float4*)(g_a2 + (size_t)row0 * H1);
    #pragma unroll
    for (int l = t; l < (64 * H1) / 4; l += 256) Xs4[l] = Ag[l];
    __syncthreads();

    float acc[8][4];
    #pragma unroll
    for (int r = 0; r < 8; r++)
        #pragma unroll
        for (int c = 0; c < 4; c++) acc[r][c] = 0.f;

    #pragma unroll 2
    for (int k = 0; k < H1; k += 4) {
        float4 xq[8];
        #pragma unroll
        for (int r = 0; r < 8; r++) xq[r] = Xs4[(ty * 8 + r) * (H1 / 4) + k / 4];
        #pragma unroll
        for (int kk = 0; kk < 4; kk++) {
            float4 w = Ws4[(k + kk) * (H2 / 4) + tx];
            #pragma unroll
            for (int r = 0; r < 8; r++) {
                float xv = (kk == 0) ? xq[r].x : (kk == 1) ? xq[r].y : (kk == 2) ? xq[r].z : xq[r].w;
                acc[r][0] += xv * w.x;
                acc[r][1] += xv * w.y;
                acc[r][2] += xv * w.z;
                acc[r][3] += xv * w.w;
            }
        }
    }

    float4 bq = ((const float4*)bias)[tx];
    float4 p  = ((const float4*)pw)[tx];
    float nn = p.x * p.x + p.y * p.y + p.z * p.z + p.w * p.w;
    #pragma unroll
    for (int off = 16; off > 0; off >>= 1) nn += __shfl_xor_sync(0xffffffffu, nn, off);
    float rn = rsqrtf(nn);

    #pragma unroll
    for (int r = 0; r < 8; r++) {
        float4 o;
        o.x = fmaxf(acc[r][0] + bq.x, 0.f);
        o.y = fmaxf(acc[r][1] + bq.y, 0.f);
        o.z = fmaxf(acc[r][2] + bq.z, 0.f);
        o.w = fmaxf(acc[r][3] + bq.w, 0.f);
        int row = row0 + ty * 8 + r;
        ((float4*)g_out2)[((size_t)row * H2 + tx * 4) / 4] = o;
        float sp = o.x * p.x + o.y * p.y + o.z * p.z + o.w * p.w;
        #pragma unroll
        for (int off = 16; off > 0; off >>= 1) sp += __shfl_xor_sync(0xffffffffu, sp, off);
        if (tx == 0) g_score[row] = sp * rn;
    }
}

// ---------------- top-K + gated global max pool + FC + log_softmax, one block per graph ----------------
__global__ void k_pool(const float* __restrict__ fcW, const float* __restrict__ fcb,
                       float* __restrict__ out) {
    __shared__ float s[NN];
    __shared__ float gate[NN];
    __shared__ int   sel[NN];
    __shared__ float red[NN];
    __shared__ float gm[H2];
    int b = blockIdx.x;
    int t = threadIdx.x;           // 512 threads
    float v = g_score[(size_t)b * NN + t];
    s[t] = v;
    __syncthreads();
    int rank = 0;
    for (int j = 0; j < NN; j++) {
        float u = s[j];
        rank += (u > v) || (u == v && j < t);
    }
    sel[t] = (rank < KSEL);
    gate[t] = tanhf(v);
    __syncthreads();
    int f = t & 127, ch = t >> 7;  // 4 chunks of 128 nodes each
    float m = -INFINITY;
    const float* base = g_out2 + ((size_t)b * NN) * H2;
    for (int i = ch * 128; i < ch * 128 + 128; i++) {
        if (sel[i]) m = fmaxf(m, base[(size_t)i * H2 + f] * gate[i]);
    }
    red[t] = m;
    __syncthreads();
    if (ch == 0) {
        gm[f] = fmaxf(fmaxf(red[f], red[f + 128]), fmaxf(red[f + 256], red[f + 384]));
    }
    __syncthreads();
    // FC + log_softmax (warp 0)
    if (t < 32) {
        float acc = -INFINITY;
        if (t < NC) {
            acc = fcb[t];
            #pragma unroll 8
            for (int k = 0; k < H2; k++) acc += gm[k] * fcW[k * NC + t];
        }
        float mx = acc;
        #pragma unroll
        for (int off = 16; off > 0; off >>= 1) mx = fmaxf(mx, __shfl_xor_sync(0xffffffffu, mx, off));
        float ev = (t < NC) ? expf(acc - mx) : 0.f;
        float sum = ev;
        #pragma unroll
        for (int off = 16; off > 0; off >>= 1) sum += __shfl_xor_sync(0xffffffffu, sum, off);
        if (t < NC) out[(size_t)b * NC + t] = acc - mx - logf(sum);
    }
}

// ---------------- launch ----------------
// hs 64KB + rs (NN+1)*4 + cols 8KB = 75780 B  -> 3 blocks/SM
#define GATHER_SMEM (NN*32*4 + (NN+1)*4 + EPG*2)

extern "C" void kernel_launch(void* const* d_in, const int* in_sizes, int n_in,
                              void* d_out, int out_size) {
    const float* x   = (const float*)d_in[0];
    const int*   ei  = (const int*)d_in[1];    // int32 (JAX x64 disabled)
    // d_in[2] = batch (unused; layout is implicit b*512+n)
    const float* W1  = (const float*)d_in[3];
    const float* b1  = (const float*)d_in[4];
    const float* W2  = (const float*)d_in[5];
    const float* b2  = (const float*)d_in[6];
    const float* pw  = (const float*)d_in[7];
    const float* fcW = (const float*)d_in[8];
    const float* fcb = (const float*)d_in[9];
    float*       out = (float*)d_out;

    static bool attr_done = false;
    if (!attr_done) {
        cudaFuncSetAttribute(k_gather_s<0>, cudaFuncAttributeMaxDynamicSharedMemorySize, GATHER_SMEM);
        cudaFuncSetAttribute(k_gather_s<1>, cudaFuncAttributeMaxDynamicSharedMemorySize, GATHER_SMEM);
        attr_done = true;
    }

    k_build<<<NB, NN>>>(ei);
    k_gemm1<<<NNODES / 32, dim3(16, 8)>>>(x, W1);
    k_gather_s<0><<<dim3(NB, 2), NN, GATHER_SMEM>>>(b1);
    k_gather_s<1><<<dim3(NB, 2), NN, GATHER_SMEM>>>(nullptr);
    k_gemm2<<<NNODES / 64, dim3(32, 8)>>>(W2, b2, pw);
    k_pool<<<NB, NN>>>(fcW, fcb, out);
}